// round 2
// baseline (speedup 1.0000x reference)
#include <cuda_runtime.h>

#define N_NODES 50000
#define IN_CH   128
#define HID     32
#define HEADS   4
#define HO      128          // HEADS*HID
#define N_E     800000
#define N_ET    850000       // + self loops

// ---------------- scratch (device globals; no allocation allowed) ----------
__device__ float g_h1 [N_NODES*HO];     // layer1 features (then reused for ELU output)
__device__ float g_as1[N_NODES*HEADS];
__device__ float g_ad1[N_NODES*HEADS];
__device__ float g_den1[N_NODES*HEADS];
__device__ float g_acc1[N_NODES*HO];
__device__ float g_h2 [N_NODES*HID];
__device__ float g_as2[N_NODES];
__device__ float g_ad2[N_NODES];
__device__ float g_den2[N_NODES];
__device__ float g_acc2[N_NODES*HID];

// ---------------- zero accumulators ----------------------------------------
__global__ void k_zero() {
    int i = blockIdx.x * blockDim.x + threadIdx.x;
    int stride = gridDim.x * blockDim.x;
    for (int j = i; j < N_NODES*HO;    j += stride) g_acc1[j] = 0.f;
    for (int j = i; j < N_NODES*HID;   j += stride) g_acc2[j] = 0.f;
    for (int j = i; j < N_NODES*HEADS; j += stride) g_den1[j] = 0.f;
    for (int j = i; j < N_NODES;       j += stride) g_den2[j] = 0.f;
}

// ---------------- GEMM1: h1 = x @ W1, plus alpha_src/alpha_dst --------------
// blockDim = 128 (4 warps). Each warp processes 4 nodes; lane owns 4 columns.
// W1 (64KB) staged in dynamic smem; x rows staged per-warp.
#define G1_TILES (N_NODES/16)   // 3125 exact
__global__ __launch_bounds__(128) void k_gemm1(
        const float* __restrict__ x, const float* __restrict__ W1,
        const float* __restrict__ a_src, const float* __restrict__ a_dst)
{
    extern __shared__ float sm[];
    float* Ws = sm;                 // 128*128
    float* xs = sm + 128*128;       // 4 warps * 4 nodes * 128 = 2048

    int t = threadIdx.x, lane = t & 31, w = t >> 5;

    // stage W1
    for (int i = t; i < 128*128/4; i += 128)
        ((float4*)Ws)[i] = ((const float4*)W1)[i];
    __syncthreads();

    for (int tile = blockIdx.x; tile < G1_TILES; tile += gridDim.x) {
        int nb = tile*16 + w*4;     // warp's first node
        float* xw = xs + w*512;
        // stage 4 x-rows
        for (int i = lane; i < 128; i += 32) {
            #pragma unroll
            for (int nd = 0; nd < 4; nd++)
                xw[nd*128 + i] = x[(nb+nd)*128 + i];
        }
        __syncwarp();

        float acc[4][4];
        #pragma unroll
        for (int nd = 0; nd < 4; nd++) { acc[nd][0]=acc[nd][1]=acc[nd][2]=acc[nd][3]=0.f; }

        #pragma unroll 4
        for (int k = 0; k < 128; k++) {
            float4 wv = *(const float4*)&Ws[k*128 + lane*4];
            #pragma unroll
            for (int nd = 0; nd < 4; nd++) {
                float xv = xw[nd*128 + k];
                acc[nd][0] += xv*wv.x; acc[nd][1] += xv*wv.y;
                acc[nd][2] += xv*wv.z; acc[nd][3] += xv*wv.w;
            }
        }

        float a0 = a_src[lane*4+0], a1 = a_src[lane*4+1], a2 = a_src[lane*4+2], a3 = a_src[lane*4+3];
        float d0 = a_dst[lane*4+0], d1 = a_dst[lane*4+1], d2 = a_dst[lane*4+2], d3 = a_dst[lane*4+3];

        #pragma unroll
        for (int nd = 0; nd < 4; nd++) {
            int n = nb + nd;
            float4 hv = make_float4(acc[nd][0], acc[nd][1], acc[nd][2], acc[nd][3]);
            *(float4*)&g_h1[n*128 + lane*4] = hv;
            float s = hv.x*a0 + hv.y*a1 + hv.z*a2 + hv.w*a3;
            float d = hv.x*d0 + hv.y*d1 + hv.z*d2 + hv.w*d3;
            // reduce within 8-lane groups (one head per group)
            s += __shfl_down_sync(0xffffffffu, s, 4, 8);
            s += __shfl_down_sync(0xffffffffu, s, 2, 8);
            s += __shfl_down_sync(0xffffffffu, s, 1, 8);
            d += __shfl_down_sync(0xffffffffu, d, 4, 8);
            d += __shfl_down_sync(0xffffffffu, d, 2, 8);
            d += __shfl_down_sync(0xffffffffu, d, 1, 8);
            if ((lane & 7) == 0) {
                g_as1[n*4 + (lane>>3)] = s;
                g_ad1[n*4 + (lane>>3)] = d;
            }
        }
        __syncwarp();
    }
}

// ---------------- edge pass 1: softmax weights + scatter-add ----------------
// one warp per edge; lane owns 4 channels (head = lane>>3)
__global__ void k_edge1(const int* __restrict__ src_idx, const int* __restrict__ dst_idx)
{
    int gw = (blockIdx.x * blockDim.x + threadIdx.x) >> 5;
    int lane = threadIdx.x & 31;
    if (gw >= N_ET) return;
    int src, dst;
    if (gw < N_E) { src = __ldg(&src_idx[gw]); dst = __ldg(&dst_idx[gw]); }
    else          { src = dst = gw - N_E; }

    int head = lane >> 3;
    float e = __ldg(&g_as1[src*4 + head]) + __ldg(&g_ad1[dst*4 + head]);
    e = (e > 0.f) ? e : 0.2f*e;           // leaky relu
    float wgt = __expf(e);                // softmax without max-shift (safe range)

    if ((lane & 7) == 0) atomicAdd(&g_den1[dst*4 + head], wgt);

    float4 hv = *(const float4*)&g_h1[src*128 + lane*4];
    float* out = &g_acc1[dst*128 + lane*4];
    atomicAdd(out+0, wgt*hv.x);
    atomicAdd(out+1, wgt*hv.y);
    atomicAdd(out+2, wgt*hv.z);
    atomicAdd(out+3, wgt*hv.w);
}

// ---------------- normalize + bias + ELU -> overwrite g_h1 ------------------
__global__ void k_norm1(const float* __restrict__ b1)
{
    int idx = blockIdx.x * blockDim.x + threadIdx.x;
    if (idx >= N_NODES*HO) return;
    int n = idx >> 7, t = idx & 127, head = t >> 5;
    float v = g_acc1[idx] / g_den1[n*4 + head] + __ldg(&b1[t]);
    v = (v > 0.f) ? v : expm1f(v);        // ELU
    g_h1[idx] = v;
}

// ---------------- GEMM2: h2 = elu(h1) @ W2, plus alphas ---------------------
// blockDim=128, warp per node, lane owns one of 32 columns
__global__ __launch_bounds__(128) void k_gemm2(
        const float* __restrict__ W2,
        const float* __restrict__ a_src, const float* __restrict__ a_dst)
{
    __shared__ float Ws[128*32];
    __shared__ float xs[4][128];
    int t = threadIdx.x, lane = t & 31, w = t >> 5;
    for (int i = t; i < 128*32/4; i += 128)
        ((float4*)Ws)[i] = ((const float4*)W2)[i];
    __syncthreads();

    int n = blockIdx.x*4 + w;
    if (n >= N_NODES) return;
    for (int i = lane; i < 128; i += 32) xs[w][i] = g_h1[n*128 + i];
    __syncwarp();

    float acc = 0.f;
    #pragma unroll 8
    for (int k = 0; k < 128; k++)
        acc += xs[w][k] * Ws[k*32 + lane];
    g_h2[n*32 + lane] = acc;

    float s = acc * __ldg(&a_src[lane]);
    float d = acc * __ldg(&a_dst[lane]);
    #pragma unroll
    for (int off = 16; off; off >>= 1) {
        s += __shfl_down_sync(0xffffffffu, s, off);
        d += __shfl_down_sync(0xffffffffu, d, off);
    }
    if (lane == 0) { g_as2[n] = s; g_ad2[n] = d; }
}

// ---------------- edge pass 2 ----------------------------------------------
__global__ void k_edge2(const int* __restrict__ src_idx, const int* __restrict__ dst_idx)
{
    int gw = (blockIdx.x * blockDim.x + threadIdx.x) >> 5;
    int lane = threadIdx.x & 31;
    if (gw >= N_ET) return;
    int src, dst;
    if (gw < N_E) { src = __ldg(&src_idx[gw]); dst = __ldg(&dst_idx[gw]); }
    else          { src = dst = gw - N_E; }

    float e = __ldg(&g_as2[src]) + __ldg(&g_ad2[dst]);
    e = (e > 0.f) ? e : 0.2f*e;
    float wgt = __expf(e);
    if (lane == 0) atomicAdd(&g_den2[dst], wgt);
    atomicAdd(&g_acc2[dst*32 + lane], wgt * g_h2[src*32 + lane]);
}

// ---------------- finalize --------------------------------------------------
__global__ void k_final(float* __restrict__ out, const float* __restrict__ b2)
{
    int idx = blockIdx.x * blockDim.x + threadIdx.x;
    if (idx >= N_NODES*HID) return;
    int n = idx >> 5, c = idx & 31;
    out[idx] = g_acc2[idx] / g_den2[n] + __ldg(&b2[c]);
}

// ---------------- launch ----------------------------------------------------
extern "C" void kernel_launch(void* const* d_in, const int* in_sizes, int n_in,
                              void* d_out, int out_size)
{
    const float* x     = (const float*)d_in[0];
    const int*   ei    = (const int*)d_in[1];      // int32 (JAX x64 disabled)
    const float* W1    = (const float*)d_in[2];
    const float* asrc1 = (const float*)d_in[3];
    const float* adst1 = (const float*)d_in[4];
    const float* b1    = (const float*)d_in[5];
    const float* W2    = (const float*)d_in[6];
    const float* asrc2 = (const float*)d_in[7];
    const float* adst2 = (const float*)d_in[8];
    const float* b2    = (const float*)d_in[9];
    float* out = (float*)d_out;

    const int* src_idx = ei;            // edge_index[0]
    const int* dst_idx = ei + N_E;      // edge_index[1]

    cudaFuncSetAttribute(k_gemm1, cudaFuncAttributeMaxDynamicSharedMemorySize,
                         (128*128 + 4*4*128) * (int)sizeof(float));

    k_zero<<<2048, 256>>>();
    k_gemm1<<<444, 128, (128*128 + 4*4*128)*sizeof(float)>>>(x, W1, asrc1, adst1);

    int edge_warps_threads_blocks = (N_ET * 32 + 255) / 256;
    k_edge1<<<edge_warps_threads_blocks, 256>>>(src_idx, dst_idx);
    k_norm1<<<(N_NODES*HO + 255)/256, 256>>>(b1);

    k_gemm2<<<(N_NODES + 3)/4, 128>>>(W2, asrc2, adst2);
    k_edge2<<<edge_warps_threads_blocks, 256>>>(src_idx, dst_idx);
    k_final<<<(N_NODES*HID + 255)/256, 256>>>(out, b2);
}

// round 5
// speedup vs baseline: 1.6736x; 1.6736x over previous
#include <cuda_runtime.h>

#define N_NODES 50000
#define IN_CH   128
#define HID     32
#define HEADS   4
#define HO      128
#define N_E     800000
#define N_ET    850000

__device__ float g_h1 [N_NODES*HO];
__device__ float g_as1[N_NODES*HEADS];
__device__ float g_ad1[N_NODES*HEADS];
__device__ float g_den1[N_NODES*HEADS];
__device__ float g_acc1[N_NODES*HO];
__device__ float g_h2 [N_NODES*HID];
__device__ float g_as2[N_NODES];
__device__ float g_ad2[N_NODES];
__device__ float g_den2[N_NODES];
__device__ float g_acc2[N_NODES*HID];

__device__ __forceinline__ void red_add_v4(float* p, float4 v) {
    asm volatile("red.global.add.v4.f32 [%0], {%1,%2,%3,%4};"
                 :: "l"(p), "f"(v.x), "f"(v.y), "f"(v.z), "f"(v.w) : "memory");
}
__device__ __forceinline__ void red_add_f(float* p, float v) {
    asm volatile("red.global.add.f32 [%0], %1;" :: "l"(p), "f"(v) : "memory");
}

// ---------------- zero accumulators ----------------------------------------
__global__ void k_zero() {
    int i = blockIdx.x * blockDim.x + threadIdx.x;
    int stride = gridDim.x * blockDim.x;
    for (int j = i; j < N_NODES*HO;    j += stride) g_acc1[j] = 0.f;
    for (int j = i; j < N_NODES*HID;   j += stride) g_acc2[j] = 0.f;
    for (int j = i; j < N_NODES*HEADS; j += stride) g_den1[j] = 0.f;
    for (int j = i; j < N_NODES;       j += stride) g_den2[j] = 0.f;
}

// ---------------- GEMM1: h1 = x @ W1 + alphas -------------------------------
#define G1_TILES (N_NODES/16)
__global__ __launch_bounds__(128) void k_gemm1(
        const float* __restrict__ x, const float* __restrict__ W1,
        const float* __restrict__ a_src, const float* __restrict__ a_dst)
{
    extern __shared__ float sm[];
    float* Ws = sm;
    float* xs = sm + 128*128;

    int t = threadIdx.x, lane = t & 31, w = t >> 5;

    for (int i = t; i < 128*128/4; i += 128)
        ((float4*)Ws)[i] = ((const float4*)W1)[i];
    __syncthreads();

    for (int tile = blockIdx.x; tile < G1_TILES; tile += gridDim.x) {
        int nb = tile*16 + w*4;
        float* xw = xs + w*512;
        for (int i = lane; i < 128; i += 32) {
            #pragma unroll
            for (int nd = 0; nd < 4; nd++)
                xw[nd*128 + i] = x[(nb+nd)*128 + i];
        }
        __syncwarp();

        float acc[4][4];
        #pragma unroll
        for (int nd = 0; nd < 4; nd++) { acc[nd][0]=acc[nd][1]=acc[nd][2]=acc[nd][3]=0.f; }

        #pragma unroll 4
        for (int k = 0; k < 128; k++) {
            float4 wv = *(const float4*)&Ws[k*128 + lane*4];
            #pragma unroll
            for (int nd = 0; nd < 4; nd++) {
                float xv = xw[nd*128 + k];
                acc[nd][0] += xv*wv.x; acc[nd][1] += xv*wv.y;
                acc[nd][2] += xv*wv.z; acc[nd][3] += xv*wv.w;
            }
        }

        float a0 = a_src[lane*4+0], a1 = a_src[lane*4+1], a2 = a_src[lane*4+2], a3 = a_src[lane*4+3];
        float d0 = a_dst[lane*4+0], d1 = a_dst[lane*4+1], d2 = a_dst[lane*4+2], d3 = a_dst[lane*4+3];

        #pragma unroll
        for (int nd = 0; nd < 4; nd++) {
            int n = nb + nd;
            float4 hv = make_float4(acc[nd][0], acc[nd][1], acc[nd][2], acc[nd][3]);
            *(float4*)&g_h1[n*128 + lane*4] = hv;
            float s = hv.x*a0 + hv.y*a1 + hv.z*a2 + hv.w*a3;
            float d = hv.x*d0 + hv.y*d1 + hv.z*d2 + hv.w*d3;
            s += __shfl_down_sync(0xffffffffu, s, 4, 8);
            s += __shfl_down_sync(0xffffffffu, s, 2, 8);
            s += __shfl_down_sync(0xffffffffu, s, 1, 8);
            d += __shfl_down_sync(0xffffffffu, d, 4, 8);
            d += __shfl_down_sync(0xffffffffu, d, 2, 8);
            d += __shfl_down_sync(0xffffffffu, d, 1, 8);
            if ((lane & 7) == 0) {
                g_as1[n*4 + (lane>>3)] = s;
                g_ad1[n*4 + (lane>>3)] = d;
            }
        }
        __syncwarp();
    }
}

// ---------------- edge pass 1: one warp per edge, v4 reductions -------------
__global__ void k_edge1(const int* __restrict__ src_idx, const int* __restrict__ dst_idx)
{
    int gw = (blockIdx.x * blockDim.x + threadIdx.x) >> 5;
    int lane = threadIdx.x & 31;
    if (gw >= N_ET) return;
    int src, dst;
    if (gw < N_E) { src = __ldg(&src_idx[gw]); dst = __ldg(&dst_idx[gw]); }
    else          { src = dst = gw - N_E; }

    int head = lane >> 3;
    float e = __ldg(&g_as1[src*4 + head]) + __ldg(&g_ad1[dst*4 + head]);
    e = (e > 0.f) ? e : 0.2f*e;
    float wgt = __expf(e);

    if ((lane & 7) == 0) red_add_f(&g_den1[dst*4 + head], wgt);

    float4 hv = *(const float4*)&g_h1[src*128 + lane*4];
    red_add_v4(&g_acc1[dst*128 + lane*4],
               make_float4(wgt*hv.x, wgt*hv.y, wgt*hv.z, wgt*hv.w));
}

// ---------------- GEMM2 (fused normalize + bias + ELU on input) -------------
__global__ __launch_bounds__(128) void k_gemm2(
        const float* __restrict__ W2, const float* __restrict__ b1,
        const float* __restrict__ a_src, const float* __restrict__ a_dst)
{
    __shared__ float Ws[128*32];
    __shared__ float xs[4][128];
    int t = threadIdx.x, lane = t & 31, w = t >> 5;
    for (int i = t; i < 128*32/4; i += 128)
        ((float4*)Ws)[i] = ((const float4*)W2)[i];
    __syncthreads();

    int n = blockIdx.x*4 + w;
    if (n >= N_NODES) return;

    // fused: v = elu(acc1/den1 + b1)
    float dinv[4];
    #pragma unroll
    for (int h = 0; h < 4; h++) dinv[h] = 1.f / g_den1[n*4 + h];
    for (int i = lane; i < 128; i += 32) {
        float v = g_acc1[n*128 + i] * dinv[i>>5] + __ldg(&b1[i]);
        xs[w][i] = (v > 0.f) ? v : expm1f(v);
    }
    __syncwarp();

    float acc = 0.f;
    #pragma unroll 8
    for (int k = 0; k < 128; k++)
        acc += xs[w][k] * Ws[k*32 + lane];
    g_h2[n*32 + lane] = acc;

    float s = acc * __ldg(&a_src[lane]);
    float d = acc * __ldg(&a_dst[lane]);
    #pragma unroll
    for (int off = 16; off; off >>= 1) {
        s += __shfl_down_sync(0xffffffffu, s, off);
        d += __shfl_down_sync(0xffffffffu, d, off);
    }
    if (lane == 0) { g_as2[n] = s; g_ad2[n] = d; }
}

// ---------------- edge pass 2: 4 edges per warp, 8 lanes/edge, v4 red -------
__global__ void k_edge2(const int* __restrict__ src_idx, const int* __restrict__ dst_idx)
{
    int gw = (blockIdx.x * blockDim.x + threadIdx.x) >> 5;  // warp id
    int lane = threadIdx.x & 31;
    int sub = lane >> 3;            // edge within warp (0..3)
    int c   = lane & 7;             // 16B chunk (0..7) -> 32 floats
    int eid = gw*4 + sub;
    if (eid >= N_ET) return;
    int src, dst;
    if (eid < N_E) { src = __ldg(&src_idx[eid]); dst = __ldg(&dst_idx[eid]); }
    else           { src = dst = eid - N_E; }

    float e = __ldg(&g_as2[src]) + __ldg(&g_ad2[dst]);
    e = (e > 0.f) ? e : 0.2f*e;
    float wgt = __expf(e);
    if (c == 0) red_add_f(&g_den2[dst], wgt);

    float4 hv = *(const float4*)&g_h2[src*32 + c*4];
    red_add_v4(&g_acc2[dst*32 + c*4],
               make_float4(wgt*hv.x, wgt*hv.y, wgt*hv.z, wgt*hv.w));
}

// ---------------- finalize --------------------------------------------------
__global__ void k_final(float* __restrict__ out, const float* __restrict__ b2)
{
    int idx = blockIdx.x * blockDim.x + threadIdx.x;
    if (idx >= N_NODES*HID) return;
    int n = idx >> 5, cch = idx & 31;
    out[idx] = g_acc2[idx] / g_den2[n] + __ldg(&b2[cch]);
}

// ---------------- launch ----------------------------------------------------
extern "C" void kernel_launch(void* const* d_in, const int* in_sizes, int n_in,
                              void* d_out, int out_size)
{
    const float* x     = (const float*)d_in[0];
    const int*   ei    = (const int*)d_in[1];
    const float* W1    = (const float*)d_in[2];
    const float* asrc1 = (const float*)d_in[3];
    const float* adst1 = (const float*)d_in[4];
    const float* b1    = (const float*)d_in[5];
    const float* W2    = (const float*)d_in[6];
    const float* asrc2 = (const float*)d_in[7];
    const float* adst2 = (const float*)d_in[8];
    const float* b2    = (const float*)d_in[9];
    float* out = (float*)d_out;

    const int* src_idx = ei;
    const int* dst_idx = ei + N_E;

    cudaFuncSetAttribute(k_gemm1, cudaFuncAttributeMaxDynamicSharedMemorySize,
                         (128*128 + 4*4*128) * (int)sizeof(float));

    k_zero<<<2048, 256>>>();
    k_gemm1<<<444, 128, (128*128 + 4*4*128)*sizeof(float)>>>(x, W1, asrc1, adst1);

    k_edge1<<<(N_ET*32 + 255)/256, 256>>>(src_idx, dst_idx);

    k_gemm2<<<(N_NODES + 3)/4, 128>>>(W2, b1, asrc2, adst2);

    k_edge2<<<((N_ET+3)/4*32 + 255)/256, 256>>>(src_idx, dst_idx);
    k_final<<<(N_NODES*HID + 255)/256, 256>>>(out, b2);
}

// round 8
// speedup vs baseline: 1.7156x; 1.0251x over previous
#include <cuda_runtime.h>

#define N_NODES 50000
#define IN_CH   128
#define HID     32
#define HEADS   4
#define HO      128
#define N_E     800000
#define N_ET    850000

// ---------------- scratch ----------------------------------------------------
__device__ float g_h1 [N_NODES*HO];      // layer1 raw features (pre-softmax)
__device__ float g_as1[N_NODES*HEADS];
__device__ float g_ad1[N_NODES*HEADS];
__device__ float g_hact[N_NODES*HO];     // layer1 aggregated+ELU output
__device__ float g_h2 [N_NODES*HID];
__device__ float g_as2[N_NODES];
__device__ float g_ad2[N_NODES];
// CSR
__device__ int g_deg [N_NODES];
__device__ int g_off [N_NODES];
__device__ int g_pos [N_NODES];
__device__ int g_srcs[N_ET];

// ---------------- CSR build --------------------------------------------------
__global__ void k_zero_deg() {
    int i = blockIdx.x * blockDim.x + threadIdx.x;
    if (i < N_NODES) g_deg[i] = 0;
}

__global__ void k_hist(const int* __restrict__ dst_idx) {
    int e = blockIdx.x * blockDim.x + threadIdx.x;
    if (e >= N_ET) return;
    int dst = (e < N_E) ? __ldg(&dst_idx[e]) : (e - N_E);
    atomicAdd(&g_deg[dst], 1);
}

// single-block exclusive scan over 50000 degrees -> g_off, g_pos
__global__ __launch_bounds__(1024) void k_scan() {
    __shared__ int ssum[1024];
    int t = threadIdx.x;
    const int PER = (N_NODES + 1023) / 1024;   // 49
    int base = t * PER;
    int s = 0;
    for (int i = 0; i < PER; i++) {
        int idx = base + i;
        if (idx < N_NODES) s += g_deg[idx];
    }
    ssum[t] = s;
    __syncthreads();
    // inclusive Hillis-Steele scan
    for (int d = 1; d < 1024; d <<= 1) {
        int add = (t >= d) ? ssum[t - d] : 0;
        __syncthreads();
        ssum[t] += add;
        __syncthreads();
    }
    int off = ssum[t] - s;   // exclusive offset for this thread's chunk
    for (int i = 0; i < PER; i++) {
        int idx = base + i;
        if (idx < N_NODES) {
            int d = g_deg[idx];
            g_off[idx] = off;
            g_pos[idx] = off;
            off += d;
        }
    }
}

__global__ void k_scatter(const int* __restrict__ src_idx, const int* __restrict__ dst_idx) {
    int e = blockIdx.x * blockDim.x + threadIdx.x;
    if (e >= N_ET) return;
    int src, dst;
    if (e < N_E) { src = __ldg(&src_idx[e]); dst = __ldg(&dst_idx[e]); }
    else         { src = dst = e - N_E; }
    int p = atomicAdd(&g_pos[dst], 1);
    g_srcs[p] = src;
}

// ---------------- GEMM1: h1 = x @ W1 + alphas --------------------------------
#define G1_TILES (N_NODES/16)
__global__ __launch_bounds__(128) void k_gemm1(
        const float* __restrict__ x, const float* __restrict__ W1,
        const float* __restrict__ a_src, const float* __restrict__ a_dst)
{
    extern __shared__ float sm[];
    float* Ws = sm;
    float* xs = sm + 128*128;

    int t = threadIdx.x, lane = t & 31, w = t >> 5;

    for (int i = t; i < 128*128/4; i += 128)
        ((float4*)Ws)[i] = ((const float4*)W1)[i];
    __syncthreads();

    for (int tile = blockIdx.x; tile < G1_TILES; tile += gridDim.x) {
        int nb = tile*16 + w*4;
        float* xw = xs + w*512;
        for (int i = lane; i < 128; i += 32) {
            #pragma unroll
            for (int nd = 0; nd < 4; nd++)
                xw[nd*128 + i] = x[(nb+nd)*128 + i];
        }
        __syncwarp();

        float acc[4][4];
        #pragma unroll
        for (int nd = 0; nd < 4; nd++) { acc[nd][0]=acc[nd][1]=acc[nd][2]=acc[nd][3]=0.f; }

        #pragma unroll 4
        for (int k = 0; k < 128; k++) {
            float4 wv = *(const float4*)&Ws[k*128 + lane*4];
            #pragma unroll
            for (int nd = 0; nd < 4; nd++) {
                float xv = xw[nd*128 + k];
                acc[nd][0] += xv*wv.x; acc[nd][1] += xv*wv.y;
                acc[nd][2] += xv*wv.z; acc[nd][3] += xv*wv.w;
            }
        }

        float a0 = a_src[lane*4+0], a1 = a_src[lane*4+1], a2 = a_src[lane*4+2], a3 = a_src[lane*4+3];
        float d0 = a_dst[lane*4+0], d1 = a_dst[lane*4+1], d2 = a_dst[lane*4+2], d3 = a_dst[lane*4+3];

        #pragma unroll
        for (int nd = 0; nd < 4; nd++) {
            int n = nb + nd;
            float4 hv = make_float4(acc[nd][0], acc[nd][1], acc[nd][2], acc[nd][3]);
            *(float4*)&g_h1[n*128 + lane*4] = hv;
            float s = hv.x*a0 + hv.y*a1 + hv.z*a2 + hv.w*a3;
            float d = hv.x*d0 + hv.y*d1 + hv.z*d2 + hv.w*d3;
            s += __shfl_down_sync(0xffffffffu, s, 4, 8);
            s += __shfl_down_sync(0xffffffffu, s, 2, 8);
            s += __shfl_down_sync(0xffffffffu, s, 1, 8);
            d += __shfl_down_sync(0xffffffffu, d, 4, 8);
            d += __shfl_down_sync(0xffffffffu, d, 2, 8);
            d += __shfl_down_sync(0xffffffffu, d, 1, 8);
            if ((lane & 7) == 0) {
                g_as1[n*4 + (lane>>3)] = s;
                g_ad1[n*4 + (lane>>3)] = d;
            }
        }
        __syncwarp();
    }
}

// ---------------- edge pass 1 (CSR): warp per dst, atomic-free ---------------
// lane owns 4 channels; head = lane>>3. Epilogue: normalize + b1 + ELU.
__global__ __launch_bounds__(256) void k_edge1_csr(const float* __restrict__ b1)
{
    int n = (blockIdx.x * blockDim.x + threadIdx.x) >> 5;
    int lane = threadIdx.x & 31;
    if (n >= N_NODES) return;
    int beg = g_off[n];
    int deg = g_deg[n];
    int head = lane >> 3;
    float ad = g_ad1[n*4 + head];

    float ax=0.f, ay=0.f, az=0.f, aw=0.f, den=0.f;

    for (int base = 0; base < deg; base += 32) {
        int rem = deg - base;
        int cnt = rem < 32 ? rem : 32;
        int s_l = (lane < cnt) ? __ldg(&g_srcs[beg + base + lane]) : 0;
        int i = 0;
        for (; i + 4 <= cnt; i += 4) {
            int s0 = __shfl_sync(0xffffffffu, s_l, i);
            int s1 = __shfl_sync(0xffffffffu, s_l, i+1);
            int s2 = __shfl_sync(0xffffffffu, s_l, i+2);
            int s3 = __shfl_sync(0xffffffffu, s_l, i+3);
            float e0 = __ldg(&g_as1[s0*4+head]) + ad;
            float e1 = __ldg(&g_as1[s1*4+head]) + ad;
            float e2 = __ldg(&g_as1[s2*4+head]) + ad;
            float e3 = __ldg(&g_as1[s3*4+head]) + ad;
            float4 h0 = *(const float4*)&g_h1[s0*128 + lane*4];
            float4 h1 = *(const float4*)&g_h1[s1*128 + lane*4];
            float4 h2 = *(const float4*)&g_h1[s2*128 + lane*4];
            float4 h3 = *(const float4*)&g_h1[s3*128 + lane*4];
            e0 = e0>0.f?e0:0.2f*e0; e1 = e1>0.f?e1:0.2f*e1;
            e2 = e2>0.f?e2:0.2f*e2; e3 = e3>0.f?e3:0.2f*e3;
            float w0 = __expf(e0), w1 = __expf(e1), w2 = __expf(e2), w3 = __expf(e3);
            den += (w0+w1) + (w2+w3);
            ax += w0*h0.x + w1*h1.x + w2*h2.x + w3*h3.x;
            ay += w0*h0.y + w1*h1.y + w2*h2.y + w3*h3.y;
            az += w0*h0.z + w1*h1.z + w2*h2.z + w3*h3.z;
            aw += w0*h0.w + w1*h1.w + w2*h2.w + w3*h3.w;
        }
        for (; i < cnt; i++) {
            int s = __shfl_sync(0xffffffffu, s_l, i);
            float e = __ldg(&g_as1[s*4+head]) + ad;
            e = e>0.f?e:0.2f*e;
            float w = __expf(e);
            den += w;
            float4 hv = *(const float4*)&g_h1[s*128 + lane*4];
            ax += w*hv.x; ay += w*hv.y; az += w*hv.z; aw += w*hv.w;
        }
    }

    float dinv = 1.f / den;     // deg >= 1 always (self loop)
    float4 bb = *(const float4*)&b1[lane*4];
    float vx = ax*dinv + bb.x, vy = ay*dinv + bb.y;
    float vz = az*dinv + bb.z, vw = aw*dinv + bb.w;
    vx = vx>0.f?vx:expm1f(vx); vy = vy>0.f?vy:expm1f(vy);
    vz = vz>0.f?vz:expm1f(vz); vw = vw>0.f?vw:expm1f(vw);
    *(float4*)&g_hact[n*128 + lane*4] = make_float4(vx, vy, vz, vw);
}

// ---------------- GEMM2: h2 = hact @ W2 + alphas (transposed smem W) ---------
__global__ __launch_bounds__(128) void k_gemm2(
        const float* __restrict__ W2,
        const float* __restrict__ a_src, const float* __restrict__ a_dst)
{
    __shared__ float WsT[32][132];   // padded, column-major: WsT[c][k] = W2[k*32+c]
    __shared__ float xs[8][128];
    int t = threadIdx.x, lane = t & 31, w = t >> 5;

    for (int i = t; i < 128*32/4; i += 128) {
        float4 v = ((const float4*)W2)[i];
        int k = i >> 3;          // 8 float4 per row of 32
        int c = (i & 7) * 4;
        WsT[c+0][k] = v.x; WsT[c+1][k] = v.y; WsT[c+2][k] = v.z; WsT[c+3][k] = v.w;
    }
    __syncthreads();

    int n0 = blockIdx.x*8 + w*2;   // 50000 divisible by 8 -> no guards
    ((float4*)xs[w*2  ])[lane] = ((const float4*)&g_hact[ n0   *128])[lane];
    ((float4*)xs[w*2+1])[lane] = ((const float4*)&g_hact[(n0+1)*128])[lane];
    __syncwarp();

    float acc0 = 0.f, acc1 = 0.f;
    #pragma unroll
    for (int k4 = 0; k4 < 32; k4++) {
        float4 wv = *(const float4*)&WsT[lane][k4*4];
        float4 xa = *(const float4*)&xs[w*2  ][k4*4];
        float4 xb = *(const float4*)&xs[w*2+1][k4*4];
        acc0 += xa.x*wv.x + xa.y*wv.y + xa.z*wv.z + xa.w*wv.w;
        acc1 += xb.x*wv.x + xb.y*wv.y + xb.z*wv.z + xb.w*wv.w;
    }
    g_h2[ n0   *32 + lane] = acc0;
    g_h2[(n0+1)*32 + lane] = acc1;

    float asl = __ldg(&a_src[lane]), adl = __ldg(&a_dst[lane]);
    float s0 = acc0*asl, d0 = acc0*adl, s1 = acc1*asl, d1 = acc1*adl;
    #pragma unroll
    for (int off = 16; off; off >>= 1) {
        s0 += __shfl_down_sync(0xffffffffu, s0, off);
        d0 += __shfl_down_sync(0xffffffffu, d0, off);
        s1 += __shfl_down_sync(0xffffffffu, s1, off);
        d1 += __shfl_down_sync(0xffffffffu, d1, off);
    }
    if (lane == 0) {
        g_as2[n0] = s0; g_ad2[n0] = d0;
        g_as2[n0+1] = s1; g_ad2[n0+1] = d1;
    }
}

// ---------------- edge pass 2 (CSR): warp per dst, writes d_out --------------
__global__ __launch_bounds__(256) void k_edge2_csr(float* __restrict__ out,
                                                   const float* __restrict__ b2)
{
    int n = (blockIdx.x * blockDim.x + threadIdx.x) >> 5;
    int lane = threadIdx.x & 31;
    if (n >= N_NODES) return;
    int beg = g_off[n];
    int deg = g_deg[n];
    float ad = g_ad2[n];

    float acc = 0.f, den = 0.f;

    for (int base = 0; base < deg; base += 32) {
        int rem = deg - base;
        int cnt = rem < 32 ? rem : 32;
        int s_l = (lane < cnt) ? __ldg(&g_srcs[beg + base + lane]) : 0;
        int i = 0;
        for (; i + 4 <= cnt; i += 4) {
            int s0 = __shfl_sync(0xffffffffu, s_l, i);
            int s1 = __shfl_sync(0xffffffffu, s_l, i+1);
            int s2 = __shfl_sync(0xffffffffu, s_l, i+2);
            int s3 = __shfl_sync(0xffffffffu, s_l, i+3);
            float e0 = __ldg(&g_as2[s0]) + ad;
            float e1 = __ldg(&g_as2[s1]) + ad;
            float e2 = __ldg(&g_as2[s2]) + ad;
            float e3 = __ldg(&g_as2[s3]) + ad;
            float h0 = __ldg(&g_h2[s0*32 + lane]);
            float h1 = __ldg(&g_h2[s1*32 + lane]);
            float h2 = __ldg(&g_h2[s2*32 + lane]);
            float h3 = __ldg(&g_h2[s3*32 + lane]);
            e0 = e0>0.f?e0:0.2f*e0; e1 = e1>0.f?e1:0.2f*e1;
            e2 = e2>0.f?e2:0.2f*e2; e3 = e3>0.f?e3:0.2f*e3;
            float w0 = __expf(e0), w1 = __expf(e1), w2 = __expf(e2), w3 = __expf(e3);
            den += (w0+w1) + (w2+w3);
            acc += w0*h0 + w1*h1 + w2*h2 + w3*h3;
        }
        for (; i < cnt; i++) {
            int s = __shfl_sync(0xffffffffu, s_l, i);
            float e = __ldg(&g_as2[s]) + ad;
            e = e>0.f?e:0.2f*e;
            float w = __expf(e);
            den += w;
            acc += w * __ldg(&g_h2[s*32 + lane]);
        }
    }

    out[n*32 + lane] = acc / den + __ldg(&b2[lane]);
}

// ---------------- launch -----------------------------------------------------
extern "C" void kernel_launch(void* const* d_in, const int* in_sizes, int n_in,
                              void* d_out, int out_size)
{
    const float* x     = (const float*)d_in[0];
    const int*   ei    = (const int*)d_in[1];
    const float* W1    = (const float*)d_in[2];
    const float* asrc1 = (const float*)d_in[3];
    const float* adst1 = (const float*)d_in[4];
    const float* b1    = (const float*)d_in[5];
    const float* W2    = (const float*)d_in[6];
    const float* asrc2 = (const float*)d_in[7];
    const float* adst2 = (const float*)d_in[8];
    const float* b2    = (const float*)d_in[9];
    float* out = (float*)d_out;

    const int* src_idx = ei;
    const int* dst_idx = ei + N_E;

    cudaFuncSetAttribute(k_gemm1, cudaFuncAttributeMaxDynamicSharedMemorySize,
                         (128*128 + 4*4*128) * (int)sizeof(float));

    // CSR build
    k_zero_deg<<<(N_NODES + 255)/256, 256>>>();
    k_hist<<<(N_ET + 255)/256, 256>>>(dst_idx);
    k_scan<<<1, 1024>>>();
    k_scatter<<<(N_ET + 255)/256, 256>>>(src_idx, dst_idx);

    // layer 1
    k_gemm1<<<444, 128, (128*128 + 4*4*128)*sizeof(float)>>>(x, W1, asrc1, adst1);
    k_edge1_csr<<<(N_NODES*32 + 255)/256, 256>>>(b1);

    // layer 2
    k_gemm2<<<N_NODES/8, 128>>>(W2, asrc2, adst2);
    k_edge2_csr<<<(N_NODES*32 + 255)/256, 256>>>(out, b2);
}

// round 9
// speedup vs baseline: 2.2159x; 1.2916x over previous
#include <cuda_runtime.h>
#include <cuda_fp16.h>

#define N_NODES 50000
#define IN_CH   128
#define HID     32
#define HEADS   4
#define HO      128
#define N_E     800000
#define N_ET    850000

// ---------------- scratch ----------------------------------------------------
__device__ __half2 g_h1h[N_NODES*64];    // layer1 raw features, fp16 (64 half2/row)
__device__ float g_as1[N_NODES*HEADS];
__device__ float g_ad1[N_NODES*HEADS];
__device__ float g_hact[N_NODES*HO];     // layer1 aggregated+ELU output (fp32)
__device__ float g_h2 [N_NODES*HID];
__device__ float g_as2[N_NODES];
__device__ float g_ad2[N_NODES];
// CSR
__device__ int g_deg [N_NODES];
__device__ int g_off [N_NODES];
__device__ int g_pos [N_NODES];
__device__ int g_srcs[N_ET];

// ---------------- CSR build --------------------------------------------------
__global__ void k_zero_deg() {
    int i = blockIdx.x * blockDim.x + threadIdx.x;
    if (i < N_NODES) g_deg[i] = 0;
}

__global__ void k_hist(const int* __restrict__ dst_idx) {
    int e = blockIdx.x * blockDim.x + threadIdx.x;
    if (e >= N_ET) return;
    int dst = (e < N_E) ? __ldg(&dst_idx[e]) : (e - N_E);
    atomicAdd(&g_deg[dst], 1);
}

__global__ __launch_bounds__(1024) void k_scan() {
    __shared__ int ssum[1024];
    int t = threadIdx.x;
    const int PER = (N_NODES + 1023) / 1024;
    int base = t * PER;
    int s = 0;
    for (int i = 0; i < PER; i++) {
        int idx = base + i;
        if (idx < N_NODES) s += g_deg[idx];
    }
    ssum[t] = s;
    __syncthreads();
    for (int d = 1; d < 1024; d <<= 1) {
        int add = (t >= d) ? ssum[t - d] : 0;
        __syncthreads();
        ssum[t] += add;
        __syncthreads();
    }
    int off = ssum[t] - s;
    for (int i = 0; i < PER; i++) {
        int idx = base + i;
        if (idx < N_NODES) {
            int d = g_deg[idx];
            g_off[idx] = off;
            g_pos[idx] = off;
            off += d;
        }
    }
}

__global__ void k_scatter(const int* __restrict__ src_idx, const int* __restrict__ dst_idx) {
    int e = blockIdx.x * blockDim.x + threadIdx.x;
    if (e >= N_ET) return;
    int src, dst;
    if (e < N_E) { src = __ldg(&src_idx[e]); dst = __ldg(&dst_idx[e]); }
    else         { src = dst = e - N_E; }
    int p = atomicAdd(&g_pos[dst], 1);
    g_srcs[p] = src;
}

// ---------------- GEMM1: h1 = x @ W1 + alphas (h1 stored fp16) ---------------
#define G1_TILES (N_NODES/16)
__global__ __launch_bounds__(128) void k_gemm1(
        const float* __restrict__ x, const float* __restrict__ W1,
        const float* __restrict__ a_src, const float* __restrict__ a_dst)
{
    extern __shared__ float sm[];
    float* Ws = sm;
    float* xs = sm + 128*128;

    int t = threadIdx.x, lane = t & 31, w = t >> 5;

    for (int i = t; i < 128*128/4; i += 128)
        ((float4*)Ws)[i] = ((const float4*)W1)[i];
    __syncthreads();

    for (int tile = blockIdx.x; tile < G1_TILES; tile += gridDim.x) {
        int nb = tile*16 + w*4;
        float* xw = xs + w*512;
        for (int i = lane; i < 128; i += 32) {
            #pragma unroll
            for (int nd = 0; nd < 4; nd++)
                xw[nd*128 + i] = x[(nb+nd)*128 + i];
        }
        __syncwarp();

        float acc[4][4];
        #pragma unroll
        for (int nd = 0; nd < 4; nd++) { acc[nd][0]=acc[nd][1]=acc[nd][2]=acc[nd][3]=0.f; }

        #pragma unroll 4
        for (int k = 0; k < 128; k++) {
            float4 wv = *(const float4*)&Ws[k*128 + lane*4];
            #pragma unroll
            for (int nd = 0; nd < 4; nd++) {
                float xv = xw[nd*128 + k];
                acc[nd][0] += xv*wv.x; acc[nd][1] += xv*wv.y;
                acc[nd][2] += xv*wv.z; acc[nd][3] += xv*wv.w;
            }
        }

        float a0 = a_src[lane*4+0], a1 = a_src[lane*4+1], a2 = a_src[lane*4+2], a3 = a_src[lane*4+3];
        float d0 = a_dst[lane*4+0], d1 = a_dst[lane*4+1], d2 = a_dst[lane*4+2], d3 = a_dst[lane*4+3];

        #pragma unroll
        for (int nd = 0; nd < 4; nd++) {
            int n = nb + nd;
            float4 hv = make_float4(acc[nd][0], acc[nd][1], acc[nd][2], acc[nd][3]);
            __half2 p0 = __floats2half2_rn(hv.x, hv.y);
            __half2 p1 = __floats2half2_rn(hv.z, hv.w);
            uint2 pk;
            pk.x = *(unsigned*)&p0;
            pk.y = *(unsigned*)&p1;
            ((uint2*)&g_h1h[n*64])[lane] = pk;

            float s = hv.x*a0 + hv.y*a1 + hv.z*a2 + hv.w*a3;
            float d = hv.x*d0 + hv.y*d1 + hv.z*d2 + hv.w*d3;
            s += __shfl_down_sync(0xffffffffu, s, 4, 8);
            s += __shfl_down_sync(0xffffffffu, s, 2, 8);
            s += __shfl_down_sync(0xffffffffu, s, 1, 8);
            d += __shfl_down_sync(0xffffffffu, d, 4, 8);
            d += __shfl_down_sync(0xffffffffu, d, 2, 8);
            d += __shfl_down_sync(0xffffffffu, d, 1, 8);
            if ((lane & 7) == 0) {
                g_as1[n*4 + (lane>>3)] = s;
                g_ad1[n*4 + (lane>>3)] = d;
            }
        }
        __syncwarp();
    }
}

// ---------------- edge pass 1 (CSR): warp per dst, fp16 gather ---------------
__global__ __launch_bounds__(256) void k_edge1_csr(const float* __restrict__ b1)
{
    int n = (blockIdx.x * blockDim.x + threadIdx.x) >> 5;
    int lane = threadIdx.x & 31;
    if (n >= N_NODES) return;
    int beg = g_off[n];
    int deg = g_deg[n];
    int head = lane >> 3;
    float ad = g_ad1[n*4 + head];

    float ax=0.f, ay=0.f, az=0.f, aw=0.f, den=0.f;

    for (int base = 0; base < deg; base += 32) {
        int rem = deg - base;
        int cnt = rem < 32 ? rem : 32;
        int s_l = (lane < cnt) ? __ldg(&g_srcs[beg + base + lane]) : 0;
        int i = 0;
        for (; i + 4 <= cnt; i += 4) {
            int s0 = __shfl_sync(0xffffffffu, s_l, i);
            int s1 = __shfl_sync(0xffffffffu, s_l, i+1);
            int s2 = __shfl_sync(0xffffffffu, s_l, i+2);
            int s3 = __shfl_sync(0xffffffffu, s_l, i+3);
            float e0 = __ldg(&g_as1[s0*4+head]) + ad;
            float e1 = __ldg(&g_as1[s1*4+head]) + ad;
            float e2 = __ldg(&g_as1[s2*4+head]) + ad;
            float e3 = __ldg(&g_as1[s3*4+head]) + ad;
            uint2 r0 = __ldg((const uint2*)&g_h1h[s0*64] + lane);
            uint2 r1 = __ldg((const uint2*)&g_h1h[s1*64] + lane);
            uint2 r2 = __ldg((const uint2*)&g_h1h[s2*64] + lane);
            uint2 r3 = __ldg((const uint2*)&g_h1h[s3*64] + lane);
            e0 = e0>0.f?e0:0.2f*e0; e1 = e1>0.f?e1:0.2f*e1;
            e2 = e2>0.f?e2:0.2f*e2; e3 = e3>0.f?e3:0.2f*e3;
            float w0 = __expf(e0), w1 = __expf(e1), w2 = __expf(e2), w3 = __expf(e3);
            den += (w0+w1) + (w2+w3);
            float2 fa, fb;
            fa = __half22float2(*(__half2*)&r0.x); fb = __half22float2(*(__half2*)&r0.y);
            ax += w0*fa.x; ay += w0*fa.y; az += w0*fb.x; aw += w0*fb.y;
            fa = __half22float2(*(__half2*)&r1.x); fb = __half22float2(*(__half2*)&r1.y);
            ax += w1*fa.x; ay += w1*fa.y; az += w1*fb.x; aw += w1*fb.y;
            fa = __half22float2(*(__half2*)&r2.x); fb = __half22float2(*(__half2*)&r2.y);
            ax += w2*fa.x; ay += w2*fa.y; az += w2*fb.x; aw += w2*fb.y;
            fa = __half22float2(*(__half2*)&r3.x); fb = __half22float2(*(__half2*)&r3.y);
            ax += w3*fa.x; ay += w3*fa.y; az += w3*fb.x; aw += w3*fb.y;
        }
        for (; i < cnt; i++) {
            int s = __shfl_sync(0xffffffffu, s_l, i);
            float e = __ldg(&g_as1[s*4+head]) + ad;
            e = e>0.f?e:0.2f*e;
            float w = __expf(e);
            den += w;
            uint2 r = __ldg((const uint2*)&g_h1h[s*64] + lane);
            float2 fa = __half22float2(*(__half2*)&r.x);
            float2 fb = __half22float2(*(__half2*)&r.y);
            ax += w*fa.x; ay += w*fa.y; az += w*fb.x; aw += w*fb.y;
        }
    }

    float dinv = 1.f / den;
    float4 bb = *(const float4*)&b1[lane*4];
    float vx = ax*dinv + bb.x, vy = ay*dinv + bb.y;
    float vz = az*dinv + bb.z, vw = aw*dinv + bb.w;
    vx = vx>0.f?vx:expm1f(vx); vy = vy>0.f?vy:expm1f(vy);
    vz = vz>0.f?vz:expm1f(vz); vw = vw>0.f?vw:expm1f(vw);
    *(float4*)&g_hact[n*128 + lane*4] = make_float4(vx, vy, vz, vw);
}

// ---------------- GEMM2: h2 = hact @ W2 + alphas -----------------------------
__global__ __launch_bounds__(128) void k_gemm2(
        const float* __restrict__ W2,
        const float* __restrict__ a_src, const float* __restrict__ a_dst)
{
    __shared__ float WsT[32][132];
    __shared__ float xs[8][128];
    int t = threadIdx.x, lane = t & 31, w = t >> 5;

    for (int i = t; i < 128*32/4; i += 128) {
        float4 v = ((const float4*)W2)[i];
        int k = i >> 3;
        int c = (i & 7) * 4;
        WsT[c+0][k] = v.x; WsT[c+1][k] = v.y; WsT[c+2][k] = v.z; WsT[c+3][k] = v.w;
    }
    __syncthreads();

    int n0 = blockIdx.x*8 + w*2;
    ((float4*)xs[w*2  ])[lane] = ((const float4*)&g_hact[ n0   *128])[lane];
    ((float4*)xs[w*2+1])[lane] = ((const float4*)&g_hact[(n0+1)*128])[lane];
    __syncwarp();

    float acc0 = 0.f, acc1 = 0.f;
    #pragma unroll
    for (int k4 = 0; k4 < 32; k4++) {
        float4 wv = *(const float4*)&WsT[lane][k4*4];
        float4 xa = *(const float4*)&xs[w*2  ][k4*4];
        float4 xb = *(const float4*)&xs[w*2+1][k4*4];
        acc0 += xa.x*wv.x + xa.y*wv.y + xa.z*wv.z + xa.w*wv.w;
        acc1 += xb.x*wv.x + xb.y*wv.y + xb.z*wv.z + xb.w*wv.w;
    }
    g_h2[ n0   *32 + lane] = acc0;
    g_h2[(n0+1)*32 + lane] = acc1;

    float asl = __ldg(&a_src[lane]), adl = __ldg(&a_dst[lane]);
    float s0 = acc0*asl, d0 = acc0*adl, s1 = acc1*asl, d1 = acc1*adl;
    #pragma unroll
    for (int off = 16; off; off >>= 1) {
        s0 += __shfl_down_sync(0xffffffffu, s0, off);
        d0 += __shfl_down_sync(0xffffffffu, d0, off);
        s1 += __shfl_down_sync(0xffffffffu, s1, off);
        d1 += __shfl_down_sync(0xffffffffu, d1, off);
    }
    if (lane == 0) {
        g_as2[n0] = s0; g_ad2[n0] = d0;
        g_as2[n0+1] = s1; g_ad2[n0+1] = d1;
    }
}

// ---------------- edge pass 2 (CSR): warp per dst, writes d_out --------------
__global__ __launch_bounds__(256) void k_edge2_csr(float* __restrict__ out,
                                                   const float* __restrict__ b2)
{
    int n = (blockIdx.x * blockDim.x + threadIdx.x) >> 5;
    int lane = threadIdx.x & 31;
    if (n >= N_NODES) return;
    int beg = g_off[n];
    int deg = g_deg[n];
    float ad = g_ad2[n];

    float acc = 0.f, den = 0.f;

    for (int base = 0; base < deg; base += 32) {
        int rem = deg - base;
        int cnt = rem < 32 ? rem : 32;
        int s_l = (lane < cnt) ? __ldg(&g_srcs[beg + base + lane]) : 0;
        int i = 0;
        for (; i + 4 <= cnt; i += 4) {
            int s0 = __shfl_sync(0xffffffffu, s_l, i);
            int s1 = __shfl_sync(0xffffffffu, s_l, i+1);
            int s2 = __shfl_sync(0xffffffffu, s_l, i+2);
            int s3 = __shfl_sync(0xffffffffu, s_l, i+3);
            float e0 = __ldg(&g_as2[s0]) + ad;
            float e1 = __ldg(&g_as2[s1]) + ad;
            float e2 = __ldg(&g_as2[s2]) + ad;
            float e3 = __ldg(&g_as2[s3]) + ad;
            float h0 = __ldg(&g_h2[s0*32 + lane]);
            float h1 = __ldg(&g_h2[s1*32 + lane]);
            float h2 = __ldg(&g_h2[s2*32 + lane]);
            float h3 = __ldg(&g_h2[s3*32 + lane]);
            e0 = e0>0.f?e0:0.2f*e0; e1 = e1>0.f?e1:0.2f*e1;
            e2 = e2>0.f?e2:0.2f*e2; e3 = e3>0.f?e3:0.2f*e3;
            float w0 = __expf(e0), w1 = __expf(e1), w2 = __expf(e2), w3 = __expf(e3);
            den += (w0+w1) + (w2+w3);
            acc += w0*h0 + w1*h1 + w2*h2 + w3*h3;
        }
        for (; i < cnt; i++) {
            int s = __shfl_sync(0xffffffffu, s_l, i);
            float e = __ldg(&g_as2[s]) + ad;
            e = e>0.f?e:0.2f*e;
            float w = __expf(e);
            den += w;
            acc += w * __ldg(&g_h2[s*32 + lane]);
        }
    }

    out[n*32 + lane] = acc / den + __ldg(&b2[lane]);
}

// ---------------- launch -----------------------------------------------------
extern "C" void kernel_launch(void* const* d_in, const int* in_sizes, int n_in,
                              void* d_out, int out_size)
{
    const float* x     = (const float*)d_in[0];
    const int*   ei    = (const int*)d_in[1];
    const float* W1    = (const float*)d_in[2];
    const float* asrc1 = (const float*)d_in[3];
    const float* adst1 = (const float*)d_in[4];
    const float* b1    = (const float*)d_in[5];
    const float* W2    = (const float*)d_in[6];
    const float* asrc2 = (const float*)d_in[7];
    const float* adst2 = (const float*)d_in[8];
    const float* b2    = (const float*)d_in[9];
    float* out = (float*)d_out;

    const int* src_idx = ei;
    const int* dst_idx = ei + N_E;

    // side stream + events for graph-level fork/join (created once, before capture)
    static cudaStream_t s_side = nullptr;
    static cudaEvent_t ev_fork = nullptr, ev_join = nullptr;
    if (!s_side) {
        cudaStreamCreateWithFlags(&s_side, cudaStreamNonBlocking);
        cudaEventCreateWithFlags(&ev_fork, cudaEventDisableTiming);
        cudaEventCreateWithFlags(&ev_join, cudaEventDisableTiming);
    }

    cudaFuncSetAttribute(k_gemm1, cudaFuncAttributeMaxDynamicSharedMemorySize,
                         (128*128 + 4*4*128) * (int)sizeof(float));

    // fork: CSR build on side stream, gemm1 on main stream
    cudaEventRecord(ev_fork, 0);
    cudaStreamWaitEvent(s_side, ev_fork, 0);

    k_zero_deg<<<(N_NODES + 255)/256, 256, 0, s_side>>>();
    k_hist<<<(N_ET + 255)/256, 256, 0, s_side>>>(dst_idx);
    k_scan<<<1, 1024, 0, s_side>>>();
    k_scatter<<<(N_ET + 255)/256, 256, 0, s_side>>>(src_idx, dst_idx);
    cudaEventRecord(ev_join, s_side);

    k_gemm1<<<444, 128, (128*128 + 4*4*128)*sizeof(float)>>>(x, W1, asrc1, adst1);

    // join: edge1 needs both gemm1 (main) and CSR (side)
    cudaStreamWaitEvent(0, ev_join, 0);

    k_edge1_csr<<<(N_NODES*32 + 255)/256, 256>>>(b1);
    k_gemm2<<<N_NODES/8, 128>>>(W2, asrc2, adst2);
    k_edge2_csr<<<(N_NODES*32 + 255)/256, 256>>>(out, b2);
}

// round 11
// speedup vs baseline: 2.3036x; 1.0396x over previous
#include <cuda_runtime.h>
#include <cuda_fp16.h>

#define N_NODES 50000
#define IN_CH   128
#define HID     32
#define HEADS   4
#define HO      128
#define N_E     800000
#define N_ET    850000

// ---------------- scratch ----------------------------------------------------
__device__ __half2 g_h1h[N_NODES*64];    // layer1 raw features, fp16
__device__ float  g_as1[N_NODES*HEADS];
__device__ float  g_ad1[N_NODES*HEADS];
__device__ __half g_h2h[N_NODES*HID];    // layer2 raw features, fp16
__device__ float  g_as2[N_NODES];
__device__ float  g_ad2[N_NODES];
// CSR
__device__ int g_deg [N_NODES];
__device__ int g_off [N_NODES];
__device__ int g_pos [N_NODES];
__device__ int g_srcs[N_ET];

// ---------------- CSR build --------------------------------------------------
__global__ void k_zero_deg() {
    int i = blockIdx.x * blockDim.x + threadIdx.x;
    if (i < N_NODES) g_deg[i] = 0;
}

__global__ void k_hist(const int* __restrict__ dst_idx) {
    int e = blockIdx.x * blockDim.x + threadIdx.x;
    if (e >= N_ET) return;
    int dst = (e < N_E) ? __ldg(&dst_idx[e]) : (e - N_E);
    atomicAdd(&g_deg[dst], 1);
}

__global__ __launch_bounds__(1024) void k_scan() {
    __shared__ int ssum[1024];
    int t = threadIdx.x;
    const int PER = (N_NODES + 1023) / 1024;
    int base = t * PER;
    int s = 0;
    for (int i = 0; i < PER; i++) {
        int idx = base + i;
        if (idx < N_NODES) s += g_deg[idx];
    }
    ssum[t] = s;
    __syncthreads();
    for (int d = 1; d < 1024; d <<= 1) {
        int add = (t >= d) ? ssum[t - d] : 0;
        __syncthreads();
        ssum[t] += add;
        __syncthreads();
    }
    int off = ssum[t] - s;
    for (int i = 0; i < PER; i++) {
        int idx = base + i;
        if (idx < N_NODES) {
            int d = g_deg[idx];
            g_off[idx] = off;
            g_pos[idx] = off;
            off += d;
        }
    }
}

__global__ void k_scatter(const int* __restrict__ src_idx, const int* __restrict__ dst_idx) {
    int e = blockIdx.x * blockDim.x + threadIdx.x;
    if (e >= N_ET) return;
    int src, dst;
    if (e < N_E) { src = __ldg(&src_idx[e]); dst = __ldg(&dst_idx[e]); }
    else         { src = dst = e - N_E; }
    int p = atomicAdd(&g_pos[dst], 1);
    g_srcs[p] = src;
}

// ---------------- GEMM1: h1 = x @ W1 + alphas (h1 stored fp16) ---------------
#define G1_TILES (N_NODES/16)
__global__ __launch_bounds__(128) void k_gemm1(
        const float* __restrict__ x, const float* __restrict__ W1,
        const float* __restrict__ a_src, const float* __restrict__ a_dst)
{
    extern __shared__ float sm[];
    float* Ws = sm;
    float* xs = sm + 128*128;

    int t = threadIdx.x, lane = t & 31, w = t >> 5;

    for (int i = t; i < 128*128/4; i += 128)
        ((float4*)Ws)[i] = ((const float4*)W1)[i];
    __syncthreads();

    for (int tile = blockIdx.x; tile < G1_TILES; tile += gridDim.x) {
        int nb = tile*16 + w*4;
        float* xw = xs + w*512;
        for (int i = lane; i < 128; i += 32) {
            #pragma unroll
            for (int nd = 0; nd < 4; nd++)
                xw[nd*128 + i] = x[(nb+nd)*128 + i];
        }
        __syncwarp();

        float acc[4][4];
        #pragma unroll
        for (int nd = 0; nd < 4; nd++) { acc[nd][0]=acc[nd][1]=acc[nd][2]=acc[nd][3]=0.f; }

        #pragma unroll 4
        for (int k = 0; k < 128; k++) {
            float4 wv = *(const float4*)&Ws[k*128 + lane*4];
            #pragma unroll
            for (int nd = 0; nd < 4; nd++) {
                float xv = xw[nd*128 + k];
                acc[nd][0] += xv*wv.x; acc[nd][1] += xv*wv.y;
                acc[nd][2] += xv*wv.z; acc[nd][3] += xv*wv.w;
            }
        }

        float a0 = a_src[lane*4+0], a1 = a_src[lane*4+1], a2 = a_src[lane*4+2], a3 = a_src[lane*4+3];
        float d0 = a_dst[lane*4+0], d1 = a_dst[lane*4+1], d2 = a_dst[lane*4+2], d3 = a_dst[lane*4+3];

        #pragma unroll
        for (int nd = 0; nd < 4; nd++) {
            int n = nb + nd;
            float4 hv = make_float4(acc[nd][0], acc[nd][1], acc[nd][2], acc[nd][3]);
            __half2 p0 = __floats2half2_rn(hv.x, hv.y);
            __half2 p1 = __floats2half2_rn(hv.z, hv.w);
            uint2 pk;
            pk.x = *(unsigned*)&p0;
            pk.y = *(unsigned*)&p1;
            ((uint2*)&g_h1h[n*64])[lane] = pk;

            float s = hv.x*a0 + hv.y*a1 + hv.z*a2 + hv.w*a3;
            float d = hv.x*d0 + hv.y*d1 + hv.z*d2 + hv.w*d3;
            s += __shfl_down_sync(0xffffffffu, s, 4, 8);
            s += __shfl_down_sync(0xffffffffu, s, 2, 8);
            s += __shfl_down_sync(0xffffffffu, s, 1, 8);
            d += __shfl_down_sync(0xffffffffu, d, 4, 8);
            d += __shfl_down_sync(0xffffffffu, d, 2, 8);
            d += __shfl_down_sync(0xffffffffu, d, 1, 8);
            if ((lane & 7) == 0) {
                g_as1[n*4 + (lane>>3)] = s;
                g_ad1[n*4 + (lane>>3)] = d;
            }
        }
        __syncwarp();
    }
}

// ---------------- fused edge pass 1 + GEMM2 ----------------------------------
// warp per dst node: aggregate (softmax num/den), normalize+b1+ELU -> hact row
// in smem, then hact @ W2 inline -> h2 (fp16) + alpha2.
__global__ __launch_bounds__(256) void k_edge1_fused(
        const float* __restrict__ b1, const float* __restrict__ W2,
        const float* __restrict__ a_src2, const float* __restrict__ a_dst2)
{
    __shared__ float WsT[32][132];   // WsT[c][k] = W2[k*32+c]
    __shared__ float xsh[8][128];

    int t = threadIdx.x, lane = t & 31, w = t >> 5;

    for (int i = t; i < 128*32/4; i += 256) {
        float4 v = ((const float4*)W2)[i];
        int k = i >> 3;
        int c = (i & 7) * 4;
        WsT[c+0][k] = v.x; WsT[c+1][k] = v.y; WsT[c+2][k] = v.z; WsT[c+3][k] = v.w;
    }
    __syncthreads();

    int n = (blockIdx.x * blockDim.x + t) >> 5;
    if (n >= N_NODES) return;
    int beg = g_off[n];
    int deg = g_deg[n];
    int head = lane >> 3;
    float ad = g_ad1[n*4 + head];

    float ax=0.f, ay=0.f, az=0.f, aw=0.f, den=0.f;

    for (int base = 0; base < deg; base += 32) {
        int rem = deg - base;
        int cnt = rem < 32 ? rem : 32;
        int s_l = (lane < cnt) ? __ldg(&g_srcs[beg + base + lane]) : 0;
        int i = 0;
        for (; i + 8 <= cnt; i += 8) {
            int ss[8];
            #pragma unroll
            for (int j = 0; j < 8; j++) ss[j] = __shfl_sync(0xffffffffu, s_l, i+j);
            float ee[8]; uint2 rr[8];
            #pragma unroll
            for (int j = 0; j < 8; j++) {
                ee[j] = __ldg(&g_as1[ss[j]*4+head]) + ad;
                rr[j] = __ldg((const uint2*)&g_h1h[ss[j]*64] + lane);
            }
            #pragma unroll
            for (int j = 0; j < 8; j++) {
                float e = ee[j];
                e = e>0.f?e:0.2f*e;
                float wg = __expf(e);
                den += wg;
                float2 fa = __half22float2(*(__half2*)&rr[j].x);
                float2 fb = __half22float2(*(__half2*)&rr[j].y);
                ax += wg*fa.x; ay += wg*fa.y; az += wg*fb.x; aw += wg*fb.y;
            }
        }
        for (; i < cnt; i++) {
            int s = __shfl_sync(0xffffffffu, s_l, i);
            float e = __ldg(&g_as1[s*4+head]) + ad;
            e = e>0.f?e:0.2f*e;
            float wg = __expf(e);
            den += wg;
            uint2 r = __ldg((const uint2*)&g_h1h[s*64] + lane);
            float2 fa = __half22float2(*(__half2*)&r.x);
            float2 fb = __half22float2(*(__half2*)&r.y);
            ax += wg*fa.x; ay += wg*fa.y; az += wg*fb.x; aw += wg*fb.y;
        }
    }

    // normalize + b1 + ELU -> hact row staged in smem
    float dinv = 1.f / den;
    float4 bb = *(const float4*)&b1[lane*4];
    float vx = ax*dinv + bb.x, vy = ay*dinv + bb.y;
    float vz = az*dinv + bb.z, vw = aw*dinv + bb.w;
    vx = vx>0.f?vx:expm1f(vx); vy = vy>0.f?vy:expm1f(vy);
    vz = vz>0.f?vz:expm1f(vz); vw = vw>0.f?vw:expm1f(vw);
    *(float4*)&xsh[w][lane*4] = make_float4(vx, vy, vz, vw);
    __syncwarp();

    // inline GEMM2: lane computes output column `lane`
    float acc = 0.f;
    #pragma unroll
    for (int k4 = 0; k4 < 32; k4++) {
        float4 wv = *(const float4*)&WsT[lane][k4*4];
        float4 xa = *(const float4*)&xsh[w][k4*4];
        acc += xa.x*wv.x + xa.y*wv.y + xa.z*wv.z + xa.w*wv.w;
    }
    g_h2h[n*32 + lane] = __float2half_rn(acc);

    float s = acc * __ldg(&a_src2[lane]);
    float d = acc * __ldg(&a_dst2[lane]);
    #pragma unroll
    for (int off = 16; off; off >>= 1) {
        s += __shfl_down_sync(0xffffffffu, s, off);
        d += __shfl_down_sync(0xffffffffu, d, off);
    }
    if (lane == 0) { g_as2[n] = s; g_ad2[n] = d; }
}

// ---------------- edge pass 2 (CSR): warp per dst, fp16 gather, writes out ---
__global__ __launch_bounds__(256) void k_edge2_csr(float* __restrict__ out,
                                                   const float* __restrict__ b2)
{
    int n = (blockIdx.x * blockDim.x + threadIdx.x) >> 5;
    int lane = threadIdx.x & 31;
    if (n >= N_NODES) return;
    int beg = g_off[n];
    int deg = g_deg[n];
    float ad = g_ad2[n];

    float acc = 0.f, den = 0.f;

    for (int base = 0; base < deg; base += 32) {
        int rem = deg - base;
        int cnt = rem < 32 ? rem : 32;
        int s_l = (lane < cnt) ? __ldg(&g_srcs[beg + base + lane]) : 0;
        int i = 0;
        for (; i + 4 <= cnt; i += 4) {
            int s0 = __shfl_sync(0xffffffffu, s_l, i);
            int s1 = __shfl_sync(0xffffffffu, s_l, i+1);
            int s2 = __shfl_sync(0xffffffffu, s_l, i+2);
            int s3 = __shfl_sync(0xffffffffu, s_l, i+3);
            float e0 = __ldg(&g_as2[s0]) + ad;
            float e1 = __ldg(&g_as2[s1]) + ad;
            float e2 = __ldg(&g_as2[s2]) + ad;
            float e3 = __ldg(&g_as2[s3]) + ad;
            float h0 = __half2float(__ldg(&g_h2h[s0*32 + lane]));
            float h1 = __half2float(__ldg(&g_h2h[s1*32 + lane]));
            float h2 = __half2float(__ldg(&g_h2h[s2*32 + lane]));
            float h3 = __half2float(__ldg(&g_h2h[s3*32 + lane]));
            e0 = e0>0.f?e0:0.2f*e0; e1 = e1>0.f?e1:0.2f*e1;
            e2 = e2>0.f?e2:0.2f*e2; e3 = e3>0.f?e3:0.2f*e3;
            float w0 = __expf(e0), w1 = __expf(e1), w2 = __expf(e2), w3 = __expf(e3);
            den += (w0+w1) + (w2+w3);
            acc += w0*h0 + w1*h1 + w2*h2 + w3*h3;
        }
        for (; i < cnt; i++) {
            int s = __shfl_sync(0xffffffffu, s_l, i);
            float e = __ldg(&g_as2[s]) + ad;
            e = e>0.f?e:0.2f*e;
            float wg = __expf(e);
            den += wg;
            acc += wg * __half2float(__ldg(&g_h2h[s*32 + lane]));
        }
    }

    out[n*32 + lane] = acc / den + __ldg(&b2[lane]);
}

// ---------------- launch -----------------------------------------------------
extern "C" void kernel_launch(void* const* d_in, const int* in_sizes, int n_in,
                              void* d_out, int out_size)
{
    const float* x     = (const float*)d_in[0];
    const int*   ei    = (const int*)d_in[1];
    const float* W1    = (const float*)d_in[2];
    const float* asrc1 = (const float*)d_in[3];
    const float* adst1 = (const float*)d_in[4];
    const float* b1    = (const float*)d_in[5];
    const float* W2    = (const float*)d_in[6];
    const float* asrc2 = (const float*)d_in[7];
    const float* adst2 = (const float*)d_in[8];
    const float* b2    = (const float*)d_in[9];
    float* out = (float*)d_out;

    const int* src_idx = ei;
    const int* dst_idx = ei + N_E;

    static cudaStream_t s_side = nullptr;
    static cudaEvent_t ev_fork = nullptr, ev_join = nullptr;
    if (!s_side) {
        cudaStreamCreateWithFlags(&s_side, cudaStreamNonBlocking);
        cudaEventCreateWithFlags(&ev_fork, cudaEventDisableTiming);
        cudaEventCreateWithFlags(&ev_join, cudaEventDisableTiming);
    }

    cudaFuncSetAttribute(k_gemm1, cudaFuncAttributeMaxDynamicSharedMemorySize,
                         (128*128 + 4*4*128) * (int)sizeof(float));

    // fork: CSR build on side stream, gemm1 on main stream
    cudaEventRecord(ev_fork, 0);
    cudaStreamWaitEvent(s_side, ev_fork, 0);

    k_zero_deg<<<(N_NODES + 255)/256, 256, 0, s_side>>>();
    k_hist<<<(N_ET + 255)/256, 256, 0, s_side>>>(dst_idx);
    k_scan<<<1, 1024, 0, s_side>>>();
    k_scatter<<<(N_ET + 255)/256, 256, 0, s_side>>>(src_idx, dst_idx);
    cudaEventRecord(ev_join, s_side);

    k_gemm1<<<444, 128, (128*128 + 4*4*128)*sizeof(float)>>>(x, W1, asrc1, adst1);

    // join: fused edge1 needs both gemm1 (main) and CSR (side)
    cudaStreamWaitEvent(0, ev_join, 0);

    k_edge1_fused<<<(N_NODES*32 + 255)/256, 256>>>(b1, W2, asrc2, adst2);
    k_edge2_csr<<<(N_NODES*32 + 255)/256, 256>>>(out, b2);
}